// round 1
// baseline (speedup 1.0000x reference)
#include <cuda_runtime.h>
#include <math.h>

#define DIMC 768
#define HEADS 12
#define HEAD_DIM 64
#define MLPD 3072
#define BATCH 2
#define SEQ 2048
#define TOKENS (BATCH*SEQ)    // 4096
#define BH (BATCH*HEADS)      // 24
#define QKV_LD (3*DIMC)       // 2304

// -------- scratch (static device globals; no allocation allowed) --------
__device__ float g_ln  [(size_t)TOKENS*DIMC];
__device__ float g_qkv [(size_t)TOKENS*QKV_LD];
__device__ float g_S   [(size_t)BH*SEQ*SEQ];       // 402 MB attention matrix
__device__ float g_attn[(size_t)TOKENS*DIMC];
__device__ float g_x1  [(size_t)TOKENS*DIMC];
__device__ float g_h   [(size_t)TOKENS*MLPD];

// ---------------- LayerNorm: one block per row, 768 elems ----------------
__global__ void ln_kernel(const float* __restrict__ x,
                          const float* __restrict__ w,
                          const float* __restrict__ b,
                          float* __restrict__ y)
{
    int row = blockIdx.x;
    int t = threadIdx.x;
    const float* xr = x + (size_t)row * DIMC;
    float*       yr = y + (size_t)row * DIMC;

    float v[3];
    float s = 0.f, ss = 0.f;
#pragma unroll
    for (int i = 0; i < 3; i++) {
        v[i] = xr[t + i*256];
        s  += v[i];
        ss += v[i]*v[i];
    }
    __shared__ float rs[256], rss[256];
    rs[t] = s; rss[t] = ss;
    __syncthreads();
    for (int o = 128; o > 0; o >>= 1) {
        if (t < o) { rs[t] += rs[t+o]; rss[t] += rss[t+o]; }
        __syncthreads();
    }
    float mu  = rs[0]  * (1.0f/DIMC);
    float var = rss[0] * (1.0f/DIMC) - mu*mu;
    float rstd = rsqrtf(var + 1e-5f);
#pragma unroll
    for (int i = 0; i < 3; i++) {
        int c = t + i*256;
        yr[c] = (v[i]-mu)*rstd*w[c] + b[c];
    }
}

// ---------------- Softmax over rows of length 2048 ----------------
__global__ void softmax_kernel(float* __restrict__ S)
{
    size_t row = blockIdx.x;
    float* p = S + row * SEQ;
    int t = threadIdx.x;

    float v[8];
    float mx = -1e30f;
#pragma unroll
    for (int i = 0; i < 8; i++) {
        v[i] = p[t + i*256];
        mx = fmaxf(mx, v[i]);
    }
    __shared__ float red[256];
    red[t] = mx;
    __syncthreads();
    for (int o = 128; o > 0; o >>= 1) {
        if (t < o) red[t] = fmaxf(red[t], red[t+o]);
        __syncthreads();
    }
    mx = red[0];
    __syncthreads();

    float s = 0.f;
#pragma unroll
    for (int i = 0; i < 8; i++) {
        v[i] = __expf(v[i] - mx);
        s += v[i];
    }
    red[t] = s;
    __syncthreads();
    for (int o = 128; o > 0; o >>= 1) {
        if (t < o) red[t] += red[t+o];
        __syncthreads();
    }
    float inv = 1.0f / red[0];
#pragma unroll
    for (int i = 0; i < 8; i++)
        p[t + i*256] = v[i] * inv;
}

// ---------------- Generic fp32 GEMM ----------------
// C[m][n] = sum_k A[m][k] * (NT ? Bt[n][k] : B[k][n])  (+bias)(gelu)(+res)(*0.125)
// blockIdx.z batched: b = z/HEADS, h = z%HEADS; operand ptr += b*offB + h*offH.
enum { ACT_NONE = 0, ACT_GELU = 1 };

template<int BM, int BN, int TM, int TN, bool NT, int ACT,
         bool HAS_BIAS, bool HAS_RES, bool SCALE>
__global__ void __launch_bounds__((BM/TM)*(BN/TN))
gemm_kernel(const float* __restrict__ A, int lda, long long aOffB, long long aOffH,
            const float* __restrict__ B, int ldb, long long bOffB, long long bOffH,
            float*       __restrict__ C, int ldc, long long cOffB, long long cOffH,
            int K,
            const float* __restrict__ bias,
            const float* __restrict__ res, int ldres)
{
    constexpr int BK = 16;
    constexpr int NTHREADS = (BM/TM)*(BN/TN);
    __shared__ float As[BK][BM];
    __shared__ float Bs[BK][BN];

    int z  = blockIdx.z;
    int bb = z / HEADS, hh = z % HEADS;
    A += (size_t)bb*aOffB + (size_t)hh*aOffH;
    B += (size_t)bb*bOffB + (size_t)hh*bOffH;
    C += (size_t)bb*cOffB + (size_t)hh*cOffH;

    const int m0 = blockIdx.y * BM;
    const int n0 = blockIdx.x * BN;
    const int tid = threadIdx.x;
    const int row0 = (tid / (BN/TN)) * TM;
    const int col0 = (tid % (BN/TN)) * TN;

    float acc[TM][TN];
#pragma unroll
    for (int i = 0; i < TM; i++)
#pragma unroll
        for (int j = 0; j < TN; j++) acc[i][j] = 0.f;

    for (int k0 = 0; k0 < K; k0 += BK) {
        // ---- load A tile (row-major, stage transposed into As[k][m]) ----
        constexpr int A_LOADS = BM*BK/4/NTHREADS;
#pragma unroll
        for (int tld = 0; tld < A_LOADS; tld++) {
            int i  = tid + tld*NTHREADS;
            int m  = i / (BK/4);
            int k4 = (i % (BK/4)) * 4;
            float4 v = *(const float4*)(A + (size_t)(m0+m)*lda + k0 + k4);
            As[k4+0][m] = v.x; As[k4+1][m] = v.y;
            As[k4+2][m] = v.z; As[k4+3][m] = v.w;
        }
        // ---- load B tile ----
        constexpr int B_LOADS = BK*BN/4/NTHREADS;
        if (!NT) {
#pragma unroll
            for (int tld = 0; tld < B_LOADS; tld++) {
                int i  = tid + tld*NTHREADS;
                int k  = i / (BN/4);
                int n4 = (i % (BN/4)) * 4;
                *(float4*)&Bs[k][n4] =
                    *(const float4*)(B + (size_t)(k0+k)*ldb + n0 + n4);
            }
        } else {
#pragma unroll
            for (int tld = 0; tld < B_LOADS; tld++) {
                int i  = tid + tld*NTHREADS;
                int n  = i / (BK/4);
                int k4 = (i % (BK/4)) * 4;
                float4 v = *(const float4*)(B + (size_t)(n0+n)*ldb + k0 + k4);
                Bs[k4+0][n] = v.x; Bs[k4+1][n] = v.y;
                Bs[k4+2][n] = v.z; Bs[k4+3][n] = v.w;
            }
        }
        __syncthreads();

#pragma unroll
        for (int kk = 0; kk < BK; kk++) {
            float a[TM], bfrag[TN];
#pragma unroll
            for (int i = 0; i < TM; i += 4)
                *(float4*)&a[i] = *(const float4*)&As[kk][row0+i];
#pragma unroll
            for (int j = 0; j < TN; j += 4)
                *(float4*)&bfrag[j] = *(const float4*)&Bs[kk][col0+j];
#pragma unroll
            for (int i = 0; i < TM; i++)
#pragma unroll
                for (int j = 0; j < TN; j++)
                    acc[i][j] += a[i]*bfrag[j];
        }
        __syncthreads();
    }

    // ---- epilogue ----
#pragma unroll
    for (int i = 0; i < TM; i++) {
        size_t crow = (size_t)(m0 + row0 + i);
#pragma unroll
        for (int j = 0; j < TN; j++) {
            float v = acc[i][j];
            if (SCALE) v *= 0.125f;                 // 1/sqrt(HEAD_DIM)
            int gn = n0 + col0 + j;
            if (HAS_BIAS) v += bias[gn];
            if (ACT == ACT_GELU)
                v = 0.5f * v * (1.0f + erff(v * 0.70710678118654752f));
            if (HAS_RES) v += res[crow*(size_t)ldres + gn];
            C[crow*(size_t)ldc + gn] = v;
        }
    }
}

// ---------------- host launcher ----------------
extern "C" void kernel_launch(void* const* d_in, const int* in_sizes, int n_in,
                              void* d_out, int out_size)
{
    const float* x      = (const float*)d_in[0];
    const float* ln1_w  = (const float*)d_in[1];
    const float* ln1_b  = (const float*)d_in[2];
    const float* qkv_w  = (const float*)d_in[3];
    const float* qkv_b  = (const float*)d_in[4];
    const float* proj_w = (const float*)d_in[5];
    const float* proj_b = (const float*)d_in[6];
    const float* ln2_w  = (const float*)d_in[7];
    const float* ln2_b  = (const float*)d_in[8];
    const float* lin1_w = (const float*)d_in[9];
    const float* lin1_b = (const float*)d_in[10];
    const float* lin2_w = (const float*)d_in[11];
    const float* lin2_b = (const float*)d_in[12];
    float* out = (float*)d_out;

    float *ln, *qkv, *S, *attn, *x1, *h;
    cudaGetSymbolAddress((void**)&ln,   g_ln);
    cudaGetSymbolAddress((void**)&qkv,  g_qkv);
    cudaGetSymbolAddress((void**)&S,    g_S);
    cudaGetSymbolAddress((void**)&attn, g_attn);
    cudaGetSymbolAddress((void**)&x1,   g_x1);
    cudaGetSymbolAddress((void**)&h,    g_h);

    const long long zero = 0;

    // 1) LN1
    ln_kernel<<<TOKENS, 256>>>(x, ln1_w, ln1_b, ln);

    // 2) QKV = ln @ qkv_w + qkv_b          [4096 x 2304]
    gemm_kernel<128,128,8,8,false,ACT_NONE,true,false,false>
        <<<dim3(QKV_LD/128, TOKENS/128, 1), 256>>>(
        ln,    DIMC,   zero, zero,
        qkv_w, QKV_LD, zero, zero,
        qkv,   QKV_LD, zero, zero,
        DIMC, qkv_b, nullptr, 0);

    // 3) S = 0.125 * Q @ K^T   per (b,h)   [2048 x 2048] x 24
    gemm_kernel<128,128,8,8,true,ACT_NONE,false,false,true>
        <<<dim3(SEQ/128, SEQ/128, BH), 256>>>(
        qkv,        QKV_LD, (long long)SEQ*QKV_LD, HEAD_DIM,     // Q
        qkv + DIMC, QKV_LD, (long long)SEQ*QKV_LD, HEAD_DIM,     // K (as Bt)
        S,          SEQ,    (long long)HEADS*SEQ*SEQ, (long long)SEQ*SEQ,
        HEAD_DIM, nullptr, nullptr, 0);

    // 4) softmax rows
    softmax_kernel<<<BH*SEQ, 256>>>(S);

    // 5) O = P @ V   per (b,h)   [2048 x 64] x 24  -> attn[4096 x 768]
    gemm_kernel<128,64,8,8,false,ACT_NONE,false,false,false>
        <<<dim3(1, SEQ/128, BH), 128>>>(
        S,            SEQ,    (long long)HEADS*SEQ*SEQ, (long long)SEQ*SEQ,
        qkv + 2*DIMC, QKV_LD, (long long)SEQ*QKV_LD, HEAD_DIM,   // V
        attn,         DIMC,   (long long)SEQ*DIMC, HEAD_DIM,
        SEQ, nullptr, nullptr, 0);

    // 6) x1 = attn @ proj_w + proj_b + x
    gemm_kernel<128,128,8,8,false,ACT_NONE,true,true,false>
        <<<dim3(DIMC/128, TOKENS/128, 1), 256>>>(
        attn,   DIMC, zero, zero,
        proj_w, DIMC, zero, zero,
        x1,     DIMC, zero, zero,
        DIMC, proj_b, x, DIMC);

    // 7) LN2
    ln_kernel<<<TOKENS, 256>>>(x1, ln2_w, ln2_b, ln);

    // 8) h = gelu(ln @ lin1_w + lin1_b)    [4096 x 3072]
    gemm_kernel<128,128,8,8,false,ACT_GELU,true,false,false>
        <<<dim3(MLPD/128, TOKENS/128, 1), 256>>>(
        ln,     DIMC, zero, zero,
        lin1_w, MLPD, zero, zero,
        h,      MLPD, zero, zero,
        DIMC, lin1_b, nullptr, 0);

    // 9) out = h @ lin2_w + lin2_b + x1
    gemm_kernel<128,128,8,8,false,ACT_NONE,true,true,false>
        <<<dim3(DIMC/128, TOKENS/128, 1), 256>>>(
        h,      MLPD, zero, zero,
        lin2_w, DIMC, zero, zero,
        out,    DIMC, zero, zero,
        MLPD, lin2_b, x1, DIMC);
}

// round 6
// speedup vs baseline: 2.3429x; 2.3429x over previous
#include <cuda_runtime.h>
#include <cuda_fp16.h>
#include <cstdint>
#include <math.h>

#define DIMC 768
#define HEADS 12
#define HD 64
#define MLPD 3072
#define BATCH 2
#define SEQ 2048
#define TOKENS (BATCH*SEQ)    // 4096
#define BH (BATCH*HEADS)      // 24
#define QKV_LD (3*DIMC)       // 2304

typedef __half h16;

// ======================= helpers =======================
__device__ __forceinline__ uint32_t smem_u32(const void* p) {
    uint32_t a;
    asm("{ .reg .u64 t; cvta.to.shared.u64 t, %1; cvt.u32.u64 %0, t; }"
        : "=r"(a) : "l"(p));
    return a;
}
__device__ __forceinline__ void ldm_x4(uint32_t (&r)[4], uint32_t addr) {
    asm volatile("ldmatrix.sync.aligned.m8n8.x4.shared.b16 {%0,%1,%2,%3}, [%4];"
        : "=r"(r[0]), "=r"(r[1]), "=r"(r[2]), "=r"(r[3]) : "r"(addr));
}
__device__ __forceinline__ void mma16816(float (&d)[4], const uint32_t (&a)[4],
                                         uint32_t b0, uint32_t b1) {
    asm volatile("mma.sync.aligned.m16n8k16.row.col.f32.f16.f16.f32 "
        "{%0,%1,%2,%3}, {%4,%5,%6,%7}, {%8,%9}, {%0,%1,%2,%3};"
        : "+f"(d[0]), "+f"(d[1]), "+f"(d[2]), "+f"(d[3])
        : "r"(a[0]), "r"(a[1]), "r"(a[2]), "r"(a[3]), "r"(b0), "r"(b1));
}
__device__ __forceinline__ void split32(float v, h16& h, h16& l) {
    h = __float2half(v);
    l = __float2half(v - __half2float(h));
}

// ======================= scratch =======================
__device__ h16   g_ln_h [(size_t)TOKENS*DIMC];
__device__ h16   g_ln_l [(size_t)TOKENS*DIMC];
__device__ h16   g_qkv_h[(size_t)TOKENS*QKV_LD];
__device__ h16   g_qkv_l[(size_t)TOKENS*QKV_LD];
__device__ float g_S    [(size_t)BH*SEQ*SEQ];
__device__ h16   g_P_h  [(size_t)BH*SEQ*SEQ];
__device__ h16   g_P_l  [(size_t)BH*SEQ*SEQ];
__device__ h16   g_Vt_h [(size_t)BH*HD*SEQ];
__device__ h16   g_Vt_l [(size_t)BH*HD*SEQ];
__device__ h16   g_at_h [(size_t)TOKENS*DIMC];
__device__ h16   g_at_l [(size_t)TOKENS*DIMC];
__device__ float g_x1   [(size_t)TOKENS*DIMC];
__device__ h16   g_hh   [(size_t)TOKENS*MLPD];
__device__ h16   g_hl   [(size_t)TOKENS*MLPD];
__device__ h16   g_wqkv_h[(size_t)QKV_LD*DIMC], g_wqkv_l[(size_t)QKV_LD*DIMC];
__device__ h16   g_wpro_h[(size_t)DIMC*DIMC],   g_wpro_l[(size_t)DIMC*DIMC];
__device__ h16   g_w1_h  [(size_t)MLPD*DIMC],   g_w1_l  [(size_t)MLPD*DIMC];
__device__ h16   g_w2_h  [(size_t)DIMC*MLPD],   g_w2_l  [(size_t)DIMC*MLPD];

// ============== weight transpose+split: W[K,N] f32 -> Wt[N,K] hi/lo fp16 ==============
__global__ void wt_kernel(const float* __restrict__ W, int K, int N,
                          h16* __restrict__ Th, h16* __restrict__ Tl)
{
    __shared__ float t[32][33];
    int nb = blockIdx.x * 32, kb = blockIdx.y * 32;
    int tx = threadIdx.x, ty = threadIdx.y;   // 32 x 8
#pragma unroll
    for (int i = 0; i < 32; i += 8)
        t[ty + i][tx] = W[(size_t)(kb + ty + i) * N + nb + tx];
    __syncthreads();
#pragma unroll
    for (int i = 0; i < 32; i += 8) {
        int n = nb + ty + i, k = kb + tx;
        h16 h, l; split32(t[tx][ty + i], h, l);
        Th[(size_t)n * K + k] = h;
        Tl[(size_t)n * K + k] = l;
    }
}

// ============== V transpose: qkv hi/lo -> Vt[z][d][s] ==============
__global__ void vt_kernel(const h16* __restrict__ Qh, const h16* __restrict__ Ql,
                          h16* __restrict__ Vh, h16* __restrict__ Vl)
{
    int z = blockIdx.x, s0 = blockIdx.y * 64;
    int bb = z / HEADS, hh = z % HEADS;
    __shared__ h16 th[64][65], tl[64][65];
    int tid = threadIdx.x;
    int d = tid & 63;
    size_t src0 = (size_t)(bb * SEQ + s0) * QKV_LD + 2 * DIMC + hh * HD;
    for (int s = tid >> 6; s < 64; s += 4) {
        size_t src = src0 + (size_t)s * QKV_LD + d;
        th[s][d] = Qh[src];
        tl[s][d] = Ql[src];
    }
    __syncthreads();
    int s = tid & 63;
    size_t dst0 = (size_t)z * HD * SEQ + s0;
    for (int dd = tid >> 6; dd < 64; dd += 4) {
        size_t dst = dst0 + (size_t)dd * SEQ + s;
        Vh[dst] = th[s][dd];
        Vl[dst] = tl[s][dd];
    }
}

// ============== LayerNorm -> split fp16 ==============
__global__ void ln_kernel(const float* __restrict__ x,
                          const float* __restrict__ w,
                          const float* __restrict__ b,
                          h16* __restrict__ yh, h16* __restrict__ yl)
{
    int row = blockIdx.x;
    int t = threadIdx.x;
    const float* xr = x + (size_t)row * DIMC;

    float v[3];
    float s = 0.f, ss = 0.f;
#pragma unroll
    for (int i = 0; i < 3; i++) {
        v[i] = xr[t + i * 256];
        s += v[i]; ss += v[i] * v[i];
    }
    __shared__ float rs[256], rss[256];
    rs[t] = s; rss[t] = ss;
    __syncthreads();
    for (int o = 128; o > 0; o >>= 1) {
        if (t < o) { rs[t] += rs[t + o]; rss[t] += rss[t + o]; }
        __syncthreads();
    }
    float mu = rs[0] * (1.0f / DIMC);
    float var = rss[0] * (1.0f / DIMC) - mu * mu;
    float rstd = rsqrtf(var + 1e-5f);
#pragma unroll
    for (int i = 0; i < 3; i++) {
        int c = t + i * 256;
        float o = (v[i] - mu) * rstd * w[c] + b[c];
        h16 h, l; split32(o, h, l);
        yh[(size_t)row * DIMC + c] = h;
        yl[(size_t)row * DIMC + c] = l;
    }
}

// ============== Softmax -> split fp16 P ==============
__global__ void softmax_kernel(const float* __restrict__ S,
                               h16* __restrict__ Ph, h16* __restrict__ Pl)
{
    size_t row = blockIdx.x;
    const float* p = S + row * SEQ;
    int t = threadIdx.x;

    float v[8];
    float mx = -1e30f;
#pragma unroll
    for (int i = 0; i < 8; i++) {
        v[i] = p[t + i * 256];
        mx = fmaxf(mx, v[i]);
    }
    __shared__ float red[256];
    red[t] = mx;
    __syncthreads();
    for (int o = 128; o > 0; o >>= 1) {
        if (t < o) red[t] = fmaxf(red[t], red[t + o]);
        __syncthreads();
    }
    mx = red[0];
    __syncthreads();
    float s = 0.f;
#pragma unroll
    for (int i = 0; i < 8; i++) { v[i] = __expf(v[i] - mx); s += v[i]; }
    red[t] = s;
    __syncthreads();
    for (int o = 128; o > 0; o >>= 1) {
        if (t < o) red[t] += red[t + o];
        __syncthreads();
    }
    float inv = 1.0f / red[0];
#pragma unroll
    for (int i = 0; i < 8; i++) {
        float pv = v[i] * inv;
        h16 h, l; split32(pv, h, l);
        Ph[row * SEQ + t + i * 256] = h;
        Pl[row * SEQ + t + i * 256] = l;
    }
}

// ======================= split-fp16 mma.sync GEMM =======================
// C[m][n] = sum_k A[m][k]*Bt[n][k]  via  AhBh + AhBl + AlBh  (fp32 accum)
enum { ACT_NONE = 0, ACT_GELU = 1 };

template<int BN, int ACT, bool HAS_BIAS, bool OUT_SPLIT, bool HAS_RES, bool SCALE>
__global__ void __launch_bounds__(256, 1)
mma_gemm(const h16* __restrict__ Ah, const h16* __restrict__ Al,
         int lda, long long aOffB, long long aOffH,
         const h16* __restrict__ Bh, const h16* __restrict__ Bl,
         int ldb, long long bOffB, long long bOffH,
         float* __restrict__ C, h16* __restrict__ Ch, h16* __restrict__ Cl,
         int ldc, long long cOffB, long long cOffH,
         int K,
         const float* __restrict__ bias,
         const float* __restrict__ res, int ldres)
{
    constexpr int BM = 128;
    constexpr int BK = 32;
    constexpr int PAD = 40;                 // padded row stride in halves (80B)
    constexpr int WARPS_N = (BN == 128) ? 4 : 2;
    constexpr int WARPS_M = 8 / WARPS_N;    // 2 or 4
    constexpr int WM = BM / WARPS_M;        // 64 or 32
    constexpr int WN = BN / WARPS_N;        // 32
    constexpr int MT = WM / 16;             // 4 or 2
    constexpr int NT = WN / 8;              // 4
    constexpr int NP = WN / 16;             // 2
    constexpr int AIT = 2;                  // 128*4/256 uint4 iters per A matrix
    constexpr int BIT = BN * 4 / 256;       // 2 or 1 per B matrix
    // stage layout (halves): Ah[128*40] Al[128*40] Bh[BN*40] Bl[BN*40]
    constexpr int AL_OFF = 128 * PAD;
    constexpr int BH_OFF = 2 * 128 * PAD;
    constexpr int BL_OFF = 2 * 128 * PAD + BN * PAD;
    constexpr int STG_H  = 2 * 128 * PAD + 2 * BN * PAD;

    extern __shared__ h16 smem[];
    const int tid = threadIdx.x;
    const int wid = tid >> 5, lane = tid & 31;
    const int wn = wid % WARPS_N, wm = wid / WARPS_N;
    const int m_w = wm * WM, n_w = wn * WN;

    const int z = blockIdx.z;
    const int bb = z / HEADS, hh = z % HEADS;
    Ah += (size_t)bb * aOffB + (size_t)hh * aOffH;
    Al += (size_t)bb * aOffB + (size_t)hh * aOffH;
    Bh += (size_t)bb * bOffB + (size_t)hh * bOffH;
    Bl += (size_t)bb * bOffB + (size_t)hh * bOffH;
    const size_t coff = (size_t)bb * cOffB + (size_t)hh * cOffH;

    const int m0 = blockIdx.y * BM;
    const int n0 = blockIdx.x * BN;

    float acc[MT][NT][4];
#pragma unroll
    for (int i = 0; i < MT; i++)
#pragma unroll
        for (int j = 0; j < NT; j++)
#pragma unroll
            for (int q = 0; q < 4; q++) acc[i][j][q] = 0.f;

    const uint32_t sb = smem_u32(smem);

    // ---- prologue: load chunk 0 into stage 0 ----
    {
        h16* d = smem;
#pragma unroll
        for (int i = 0; i < AIT; i++) {
            int idx = tid + i * 256, r = idx >> 2, cc = idx & 3;
            size_t src = (size_t)(m0 + r) * lda + cc * 8;
            *(uint4*)(d + r * PAD + cc * 8)          = *(const uint4*)(Ah + src);
            *(uint4*)(d + AL_OFF + r * PAD + cc * 8) = *(const uint4*)(Al + src);
        }
#pragma unroll
        for (int i = 0; i < BIT; i++) {
            int idx = tid + i * 256, r = idx >> 2, cc = idx & 3;
            size_t src = (size_t)(n0 + r) * ldb + cc * 8;
            *(uint4*)(d + BH_OFF + r * PAD + cc * 8) = *(const uint4*)(Bh + src);
            *(uint4*)(d + BL_OFF + r * PAD + cc * 8) = *(const uint4*)(Bl + src);
        }
    }
    __syncthreads();

    const int NC = K / BK;
    for (int c = 0; c < NC; ++c) {
        const int cur = c & 1;
        const bool pre = (c + 1 < NC);

        // ---- prefetch next chunk into registers ----
        uint4 rAh[AIT], rAl[AIT], rBh[BIT], rBl[BIT];
        if (pre) {
            const int k0n = (c + 1) * BK;
#pragma unroll
            for (int i = 0; i < AIT; i++) {
                int idx = tid + i * 256, r = idx >> 2, cc = idx & 3;
                size_t src = (size_t)(m0 + r) * lda + k0n + cc * 8;
                rAh[i] = *(const uint4*)(Ah + src);
                rAl[i] = *(const uint4*)(Al + src);
            }
#pragma unroll
            for (int i = 0; i < BIT; i++) {
                int idx = tid + i * 256, r = idx >> 2, cc = idx & 3;
                size_t src = (size_t)(n0 + r) * ldb + k0n + cc * 8;
                rBh[i] = *(const uint4*)(Bh + src);
                rBl[i] = *(const uint4*)(Bl + src);
            }
        }

        // ---- compute on stage cur ----
        {
            const uint32_t base = sb + (uint32_t)cur * STG_H * 2;
#pragma unroll
            for (int ks = 0; ks < 2; ks++) {
                uint32_t afh[MT][4], afl[MT][4];
                uint32_t bh[NT][2], bl[NT][2];
                const int arow = m_w + (lane & 15);
                const int akoff = ks * 16 + ((lane >> 4) << 3);
#pragma unroll
                for (int mi = 0; mi < MT; mi++) {
                    uint32_t ad = base + (uint32_t)((arow + mi * 16) * PAD + akoff) * 2;
                    ldm_x4(afh[mi], ad);
                    ldm_x4(afl[mi], ad + AL_OFF * 2);
                }
                const int brow = n_w + (lane & 7) + ((lane >> 4) << 3);
                const int bkoff = ks * 16 + ((lane >> 3) & 1) * 8;
#pragma unroll
                for (int np = 0; np < NP; np++) {
                    uint32_t bd = base + BH_OFF * 2
                                + (uint32_t)((brow + np * 16) * PAD + bkoff) * 2;
                    uint32_t t4[4];
                    ldm_x4(t4, bd);
                    bh[np*2][0] = t4[0]; bh[np*2][1] = t4[1];
                    bh[np*2+1][0] = t4[2]; bh[np*2+1][1] = t4[3];
                    ldm_x4(t4, bd + (BL_OFF - BH_OFF) * 2);
                    bl[np*2][0] = t4[0]; bl[np*2][1] = t4[1];
                    bl[np*2+1][0] = t4[2]; bl[np*2+1][1] = t4[3];
                }
                // 3 passes, tiles independent within each pass
#pragma unroll
                for (int mi = 0; mi < MT; mi++)
#pragma unroll
                    for (int ni = 0; ni < NT; ni++)
                        mma16816(acc[mi][ni], afh[mi], bh[ni][0], bh[ni][1]);
#pragma unroll
                for (int mi = 0; mi < MT; mi++)
#pragma unroll
                    for (int ni = 0; ni < NT; ni++)
                        mma16816(acc[mi][ni], afh[mi], bl[ni][0], bl[ni][1]);
#pragma unroll
                for (int mi = 0; mi < MT; mi++)
#pragma unroll
                    for (int ni = 0; ni < NT; ni++)
                        mma16816(acc[mi][ni], afl[mi], bh[ni][0], bh[ni][1]);
            }
        }

        // ---- store prefetched regs into other stage ----
        if (pre) {
            h16* d = smem + (cur ^ 1) * STG_H;
#pragma unroll
            for (int i = 0; i < AIT; i++) {
                int idx = tid + i * 256, r = idx >> 2, cc = idx & 3;
                *(uint4*)(d + r * PAD + cc * 8)          = rAh[i];
                *(uint4*)(d + AL_OFF + r * PAD + cc * 8) = rAl[i];
            }
#pragma unroll
            for (int i = 0; i < BIT; i++) {
                int idx = tid + i * 256, r = idx >> 2, cc = idx & 3;
                *(uint4*)(d + BH_OFF + r * PAD + cc * 8) = rBh[i];
                *(uint4*)(d + BL_OFF + r * PAD + cc * 8) = rBl[i];
            }
        }
        __syncthreads();
    }

    // ---- epilogue ----
#pragma unroll
    for (int mi = 0; mi < MT; mi++) {
#pragma unroll
        for (int ni = 0; ni < NT; ni++) {
            int row0 = m0 + m_w + mi * 16 + (lane >> 2);
            int col  = n0 + n_w + ni * 8 + 2 * (lane & 3);
#pragma unroll
            for (int half = 0; half < 2; half++) {
                int row = row0 + half * 8;
                float v0 = acc[mi][ni][half * 2 + 0];
                float v1 = acc[mi][ni][half * 2 + 1];
                if (SCALE) { v0 *= 0.125f; v1 *= 0.125f; }
                if (HAS_BIAS) {
                    float2 bb = *(const float2*)&bias[col];
                    v0 += bb.x; v1 += bb.y;
                }
                if (ACT == ACT_GELU) {
                    v0 = 0.5f * v0 * (1.0f + erff(v0 * 0.70710678118654752f));
                    v1 = 0.5f * v1 * (1.0f + erff(v1 * 0.70710678118654752f));
                }
                if (HAS_RES) {
                    float2 rr = *(const float2*)&res[(size_t)row * ldres + col];
                    v0 += rr.x; v1 += rr.y;
                }
                size_t idx = coff + (size_t)row * ldc + col;
                if (!OUT_SPLIT) {
                    *(float2*)&C[idx] = make_float2(v0, v1);
                } else {
                    h16 h0, l0, h1, l1;
                    split32(v0, h0, l0);
                    split32(v1, h1, l1);
                    __half2 ph; ph.x = h0; ph.y = h1;
                    __half2 pl; pl.x = l0; pl.y = l1;
                    *(__half2*)&Ch[idx] = ph;
                    *(__half2*)&Cl[idx] = pl;
                }
            }
        }
    }
}

// ======================= host launcher =======================
extern "C" void kernel_launch(void* const* d_in, const int* in_sizes, int n_in,
                              void* d_out, int out_size)
{
    const float* x      = (const float*)d_in[0];
    const float* ln1_w  = (const float*)d_in[1];
    const float* ln1_b  = (const float*)d_in[2];
    const float* qkv_w  = (const float*)d_in[3];
    const float* qkv_b  = (const float*)d_in[4];
    const float* proj_w = (const float*)d_in[5];
    const float* proj_b = (const float*)d_in[6];
    const float* ln2_w  = (const float*)d_in[7];
    const float* ln2_b  = (const float*)d_in[8];
    const float* lin1_w = (const float*)d_in[9];
    const float* lin1_b = (const float*)d_in[10];
    const float* lin2_w = (const float*)d_in[11];
    const float* lin2_b = (const float*)d_in[12];
    float* out = (float*)d_out;

    h16 *ln_h, *ln_l, *qkv_h, *qkv_l, *P_h, *P_l, *Vt_h, *Vt_l, *at_h, *at_l, *h_h, *h_l;
    h16 *wqkv_h, *wqkv_l, *wpro_h, *wpro_l, *w1_h, *w1_l, *w2_h, *w2_l;
    float *S, *x1;
    cudaGetSymbolAddress((void**)&ln_h, g_ln_h);   cudaGetSymbolAddress((void**)&ln_l, g_ln_l);
    cudaGetSymbolAddress((void**)&qkv_h, g_qkv_h); cudaGetSymbolAddress((void**)&qkv_l, g_qkv_l);
    cudaGetSymbolAddress((void**)&S, g_S);
    cudaGetSymbolAddress((void**)&P_h, g_P_h);     cudaGetSymbolAddress((void**)&P_l, g_P_l);
    cudaGetSymbolAddress((void**)&Vt_h, g_Vt_h);   cudaGetSymbolAddress((void**)&Vt_l, g_Vt_l);
    cudaGetSymbolAddress((void**)&at_h, g_at_h);   cudaGetSymbolAddress((void**)&at_l, g_at_l);
    cudaGetSymbolAddress((void**)&x1, g_x1);
    cudaGetSymbolAddress((void**)&h_h, g_hh);      cudaGetSymbolAddress((void**)&h_l, g_hl);
    cudaGetSymbolAddress((void**)&wqkv_h, g_wqkv_h); cudaGetSymbolAddress((void**)&wqkv_l, g_wqkv_l);
    cudaGetSymbolAddress((void**)&wpro_h, g_wpro_h); cudaGetSymbolAddress((void**)&wpro_l, g_wpro_l);
    cudaGetSymbolAddress((void**)&w1_h, g_w1_h);   cudaGetSymbolAddress((void**)&w1_l, g_w1_l);
    cudaGetSymbolAddress((void**)&w2_h, g_w2_h);   cudaGetSymbolAddress((void**)&w2_l, g_w2_l);

    // dyn smem: (2*128*40 + 2*BN*40)*2B per stage, x2 stages
    const int SM128 = 2 * (2 * 128 * 40 + 2 * 128 * 40) * 2;  // 81920
    const int SM64  = 2 * (2 * 128 * 40 + 2 * 64 * 40) * 2;   // 61440

    auto* kQKV  = mma_gemm<128, ACT_NONE, true,  true,  false, false>;
    auto* kQK   = mma_gemm<128, ACT_NONE, false, false, false, true >;
    auto* kPV   = mma_gemm<64,  ACT_NONE, false, true,  false, false>;
    auto* kPROJ = mma_gemm<128, ACT_NONE, true,  false, true,  false>; // also lin2
    auto* kLIN1 = mma_gemm<128, ACT_GELU, true,  true,  false, false>;

    cudaFuncSetAttribute(kQKV,  cudaFuncAttributeMaxDynamicSharedMemorySize, SM128);
    cudaFuncSetAttribute(kQK,   cudaFuncAttributeMaxDynamicSharedMemorySize, SM128);
    cudaFuncSetAttribute(kPV,   cudaFuncAttributeMaxDynamicSharedMemorySize, SM64);
    cudaFuncSetAttribute(kPROJ, cudaFuncAttributeMaxDynamicSharedMemorySize, SM128);
    cudaFuncSetAttribute(kLIN1, cudaFuncAttributeMaxDynamicSharedMemorySize, SM128);

    const long long Z0 = 0;

    // 0) weight transposes+splits
    wt_kernel<<<dim3(QKV_LD/32, DIMC/32), dim3(32,8)>>>(qkv_w,  DIMC, QKV_LD, wqkv_h, wqkv_l);
    wt_kernel<<<dim3(DIMC/32,   DIMC/32), dim3(32,8)>>>(proj_w, DIMC, DIMC,   wpro_h, wpro_l);
    wt_kernel<<<dim3(MLPD/32,   DIMC/32), dim3(32,8)>>>(lin1_w, DIMC, MLPD,   w1_h,   w1_l);
    wt_kernel<<<dim3(DIMC/32,   MLPD/32), dim3(32,8)>>>(lin2_w, MLPD, DIMC,   w2_h,   w2_l);

    // 1) LN1
    ln_kernel<<<TOKENS, 256>>>(x, ln1_w, ln1_b, ln_h, ln_l);

    // 2) qkv = ln @ qkv_w + qkv_b   (split out)
    kQKV<<<dim3(QKV_LD/128, TOKENS/128, 1), 256, SM128>>>(
        ln_h, ln_l, DIMC, Z0, Z0,
        wqkv_h, wqkv_l, DIMC, Z0, Z0,
        nullptr, qkv_h, qkv_l, QKV_LD, Z0, Z0,
        DIMC, qkv_b, nullptr, 0);

    // 2b) V transpose
    vt_kernel<<<dim3(BH, SEQ/64), 256>>>(qkv_h, qkv_l, Vt_h, Vt_l);

    // 3) S = 0.125 * Q @ K^T
    kQK<<<dim3(SEQ/128, SEQ/128, BH), 256, SM128>>>(
        qkv_h, qkv_l, QKV_LD, (long long)SEQ*QKV_LD, (long long)HD,
        qkv_h + DIMC, qkv_l + DIMC, QKV_LD, (long long)SEQ*QKV_LD, (long long)HD,
        S, nullptr, nullptr, SEQ, (long long)HEADS*SEQ*SEQ, (long long)SEQ*SEQ,
        HD, nullptr, nullptr, 0);

    // 4) softmax (split out)
    softmax_kernel<<<BH*SEQ, 256>>>(S, P_h, P_l);

    // 5) attn = P @ V  (split out)
    kPV<<<dim3(1, SEQ/128, BH), 256, SM64>>>(
        P_h, P_l, SEQ, (long long)HEADS*SEQ*SEQ, (long long)SEQ*SEQ,
        Vt_h, Vt_l, SEQ, (long long)HEADS*HD*SEQ, (long long)HD*SEQ,
        nullptr, at_h, at_l, DIMC, (long long)SEQ*DIMC, (long long)HD,
        SEQ, nullptr, nullptr, 0);

    // 6) x1 = attn @ proj_w + proj_b + x
    kPROJ<<<dim3(DIMC/128, TOKENS/128, 1), 256, SM128>>>(
        at_h, at_l, DIMC, Z0, Z0,
        wpro_h, wpro_l, DIMC, Z0, Z0,
        x1, nullptr, nullptr, DIMC, Z0, Z0,
        DIMC, proj_b, x, DIMC);

    // 7) LN2
    ln_kernel<<<TOKENS, 256>>>(x1, ln2_w, ln2_b, ln_h, ln_l);

    // 8) h = gelu(ln @ lin1_w + lin1_b)  (split out)
    kLIN1<<<dim3(MLPD/128, TOKENS/128, 1), 256, SM128>>>(
        ln_h, ln_l, DIMC, Z0, Z0,
        w1_h, w1_l, DIMC, Z0, Z0,
        nullptr, h_h, h_l, MLPD, Z0, Z0,
        DIMC, lin1_b, nullptr, 0);

    // 9) out = h @ lin2_w + lin2_b + x1
    kPROJ<<<dim3(DIMC/128, TOKENS/128, 1), 256, SM128>>>(
        h_h, h_l, MLPD, Z0, Z0,
        w2_h, w2_l, MLPD, Z0, Z0,
        out, nullptr, nullptr, DIMC, Z0, Z0,
        MLPD, lin2_b, x1, DIMC);
}

// round 8
// speedup vs baseline: 3.1124x; 1.3284x over previous
#include <cuda_runtime.h>
#include <cuda_fp16.h>
#include <cstdint>
#include <math.h>

#define DIMC 768
#define HEADS 12
#define HD 64
#define MLPD 3072
#define BATCH 2
#define SEQ 2048
#define TOKENS (BATCH*SEQ)    // 4096
#define BH (BATCH*HEADS)      // 24
#define QKV_LD (3*DIMC)       // 2304

typedef __half h16;

// ======================= helpers =======================
__device__ __forceinline__ uint32_t smem_u32(const void* p) {
    uint32_t a;
    asm("{ .reg .u64 t; cvta.to.shared.u64 t, %1; cvt.u32.u64 %0, t; }"
        : "=r"(a) : "l"(p));
    return a;
}
__device__ __forceinline__ void ldm_x4(uint32_t (&r)[4], uint32_t addr) {
    asm volatile("ldmatrix.sync.aligned.m8n8.x4.shared.b16 {%0,%1,%2,%3}, [%4];"
        : "=r"(r[0]), "=r"(r[1]), "=r"(r[2]), "=r"(r[3]) : "r"(addr));
}
__device__ __forceinline__ void ldm_x4_t(uint32_t (&r)[4], uint32_t addr) {
    asm volatile("ldmatrix.sync.aligned.m8n8.x4.trans.shared.b16 {%0,%1,%2,%3}, [%4];"
        : "=r"(r[0]), "=r"(r[1]), "=r"(r[2]), "=r"(r[3]) : "r"(addr));
}
__device__ __forceinline__ void mma16816(float (&d)[4], const uint32_t (&a)[4],
                                         uint32_t b0, uint32_t b1) {
    asm volatile("mma.sync.aligned.m16n8k16.row.col.f32.f16.f16.f32 "
        "{%0,%1,%2,%3}, {%4,%5,%6,%7}, {%8,%9}, {%0,%1,%2,%3};"
        : "+f"(d[0]), "+f"(d[1]), "+f"(d[2]), "+f"(d[3])
        : "r"(a[0]), "r"(a[1]), "r"(a[2]), "r"(a[3]), "r"(b0), "r"(b1));
}
__device__ __forceinline__ void split32(float v, h16& h, h16& l) {
    h = __float2half(v);
    l = __float2half(v - __half2float(h));
}
__device__ __forceinline__ void cp16(uint32_t dst, const void* src) {
    asm volatile("cp.async.cg.shared.global [%0], [%1], 16;"
                 :: "r"(dst), "l"(src));
}
#define CP_COMMIT() asm volatile("cp.async.commit_group;" ::: "memory")
#define CP_WAIT0()  asm volatile("cp.async.wait_group 0;" ::: "memory")

// pack two floats into split fp16x2 (hi reg returned, lo via ref)
__device__ __forceinline__ uint32_t pack_split(float a, float b, uint32_t& lo) {
    h16 ah, al, bh, bl;
    split32(a, ah, al);
    split32(b, bh, bl);
    __half2 H; H.x = ah; H.y = bh;
    __half2 L; L.x = al; L.y = bl;
    lo = *(uint32_t*)&L;
    return *(uint32_t*)&H;
}

// ======================= scratch =======================
__device__ h16   g_ln_h [(size_t)TOKENS*DIMC];
__device__ h16   g_ln_l [(size_t)TOKENS*DIMC];
__device__ h16   g_qkv_h[(size_t)TOKENS*QKV_LD];
__device__ h16   g_qkv_l[(size_t)TOKENS*QKV_LD];
__device__ h16   g_at_h [(size_t)TOKENS*DIMC];
__device__ h16   g_at_l [(size_t)TOKENS*DIMC];
__device__ float g_x1   [(size_t)TOKENS*DIMC];
__device__ h16   g_hh   [(size_t)TOKENS*MLPD];
__device__ h16   g_hl   [(size_t)TOKENS*MLPD];
__device__ h16   g_wqkv_h[(size_t)QKV_LD*DIMC], g_wqkv_l[(size_t)QKV_LD*DIMC];
__device__ h16   g_wpro_h[(size_t)DIMC*DIMC],   g_wpro_l[(size_t)DIMC*DIMC];
__device__ h16   g_w1_h  [(size_t)MLPD*DIMC],   g_w1_l  [(size_t)MLPD*DIMC];
__device__ h16   g_w2_h  [(size_t)DIMC*MLPD],   g_w2_l  [(size_t)DIMC*MLPD];

// ============== weight transpose+split: W[K,N] f32 -> Wt[N,K] hi/lo fp16 ==============
__global__ void wt_kernel(const float* __restrict__ W, int K, int N,
                          h16* __restrict__ Th, h16* __restrict__ Tl)
{
    __shared__ float t[32][33];
    int nb = blockIdx.x * 32, kb = blockIdx.y * 32;
    int tx = threadIdx.x, ty = threadIdx.y;   // 32 x 8
#pragma unroll
    for (int i = 0; i < 32; i += 8)
        t[ty + i][tx] = W[(size_t)(kb + ty + i) * N + nb + tx];
    __syncthreads();
#pragma unroll
    for (int i = 0; i < 32; i += 8) {
        int n = nb + ty + i, k = kb + tx;
        h16 h, l; split32(t[tx][ty + i], h, l);
        Th[(size_t)n * K + k] = h;
        Tl[(size_t)n * K + k] = l;
    }
}

// ============== LayerNorm -> split fp16 ==============
__global__ void ln_kernel(const float* __restrict__ x,
                          const float* __restrict__ w,
                          const float* __restrict__ b,
                          h16* __restrict__ yh, h16* __restrict__ yl)
{
    int row = blockIdx.x;
    int t = threadIdx.x;
    const float* xr = x + (size_t)row * DIMC;

    float v[3];
    float s = 0.f, ss = 0.f;
#pragma unroll
    for (int i = 0; i < 3; i++) {
        v[i] = xr[t + i * 256];
        s += v[i]; ss += v[i] * v[i];
    }
    __shared__ float rs[256], rss[256];
    rs[t] = s; rss[t] = ss;
    __syncthreads();
    for (int o = 128; o > 0; o >>= 1) {
        if (t < o) { rs[t] += rs[t + o]; rss[t] += rss[t + o]; }
        __syncthreads();
    }
    float mu = rs[0] * (1.0f / DIMC);
    float var = rss[0] * (1.0f / DIMC) - mu * mu;
    float rstd = rsqrtf(var + 1e-5f);
#pragma unroll
    for (int i = 0; i < 3; i++) {
        int c = t + i * 256;
        float o = (v[i] - mu) * rstd * w[c] + b[c];
        h16 h, l; split32(o, h, l);
        yh[(size_t)row * DIMC + c] = h;
        yl[(size_t)row * DIMC + c] = l;
    }
}

// ======================= fused flash attention =======================
// grid: (SEQ/128, BH). One CTA: 128 queries x full key range for one (b,h).
// 8 warps, each owns 16 query rows. Split-fp16 3-pass mma throughout.
__global__ void __launch_bounds__(256, 1)
fattn_kernel(const h16* __restrict__ qkvh, const h16* __restrict__ qkvl,
             h16* __restrict__ Oh, h16* __restrict__ Ol)
{
    constexpr int PAD = 72;                  // halves per tile row (144 B)
    constexpr int MSZ = 128 * PAD;           // halves per 128x64 matrix
    constexpr int KV_OFF = 2 * MSZ;          // after Qh, Ql
    constexpr int STG = 4 * MSZ;             // Kh,Kl,Vh,Vl per stage
    constexpr float SM = 0.125f;

    extern __shared__ h16 smem[];
    const uint32_t sb = smem_u32(smem);
    const int tid = threadIdx.x;
    const int wid = tid >> 5, lane = tid & 31;
    const int m_w = wid * 16;

    const int z = blockIdx.y;
    const int bb = z / HEADS, hh = z % HEADS;
    const int q0 = blockIdx.x * 128;
    const size_t tokbase = (size_t)bb * SEQ;
    const size_t hoff = (size_t)hh * HD;

    // ---- prologue: async-load Q tile + KV tile 0 ----
#pragma unroll
    for (int i = 0; i < 4; i++) {
        int idx = tid + i * 256;
        int r = idx >> 3, c = idx & 7;
        size_t row = (tokbase + q0 + r) * QKV_LD + hoff + c * 8;
        uint32_t d = sb + (uint32_t)(r * PAD + c * 8) * 2;
        cp16(d,            qkvh + row);
        cp16(d + MSZ * 2,  qkvl + row);
    }
#pragma unroll
    for (int i = 0; i < 4; i++) {
        int idx = tid + i * 256;
        int r = idx >> 3, c = idx & 7;
        size_t row = (tokbase + r) * QKV_LD + hoff + c * 8;
        uint32_t d = sb + (uint32_t)(KV_OFF + r * PAD + c * 8) * 2;
        cp16(d,               qkvh + row + DIMC);
        cp16(d + MSZ * 2,     qkvl + row + DIMC);
        cp16(d + 2 * MSZ * 2, qkvh + row + 2 * DIMC);
        cp16(d + 3 * MSZ * 2, qkvl + row + 2 * DIMC);
    }
    CP_COMMIT();
    CP_WAIT0();
    __syncthreads();

    // ---- load Q fragments (resident across whole loop) ----
    uint32_t qfh[4][4], qfl[4][4];
    {
        const int arow = m_w + (lane & 15);
#pragma unroll
        for (int kc = 0; kc < 4; kc++) {
            const int ak = kc * 16 + ((lane >> 4) << 3);
            uint32_t ad = sb + (uint32_t)(arow * PAD + ak) * 2;
            ldm_x4(qfh[kc], ad);
            ldm_x4(qfl[kc], ad + MSZ * 2);
        }
    }

    float O[8][4];
#pragma unroll
    for (int i = 0; i < 8; i++)
#pragma unroll
        for (int q = 0; q < 4; q++) O[i][q] = 0.f;
    float m0 = -1e30f, m1 = -1e30f, l0 = 0.f, l1 = 0.f;

    const int NT = SEQ / 128;
    for (int t = 0; t < NT; ++t) {
        const int cur = t & 1;

        // ---- prefetch next KV tile into other stage ----
        if (t + 1 < NT) {
            const int s0n = (t + 1) * 128;
            uint32_t base = sb + (uint32_t)(KV_OFF + (cur ^ 1) * STG) * 2;
#pragma unroll
            for (int i = 0; i < 4; i++) {
                int idx = tid + i * 256;
                int r = idx >> 3, c = idx & 7;
                size_t row = (tokbase + s0n + r) * QKV_LD + hoff + c * 8;
                uint32_t d = base + (uint32_t)(r * PAD + c * 8) * 2;
                cp16(d,               qkvh + row + DIMC);
                cp16(d + MSZ * 2,     qkvl + row + DIMC);
                cp16(d + 2 * MSZ * 2, qkvh + row + 2 * DIMC);
                cp16(d + 3 * MSZ * 2, qkvl + row + 2 * DIMC);
            }
            CP_COMMIT();
        }

        const uint32_t kb = sb + (uint32_t)(KV_OFF + cur * STG) * 2;
        const uint32_t vb = kb + 2 * MSZ * 2;

        // ---- S = Q @ K^T (128x128), 3-pass split ----
        float acc[16][4];
#pragma unroll
        for (int i = 0; i < 16; i++)
#pragma unroll
            for (int q = 0; q < 4; q++) acc[i][q] = 0.f;

#pragma unroll
        for (int np = 0; np < 8; np++) {
            const int brow = np * 16 + (lane & 7) + ((lane >> 4) << 3);
#pragma unroll
            for (int kc = 0; kc < 4; kc++) {
                const int bk = kc * 16 + ((lane >> 3) & 1) * 8;
                uint32_t ad = kb + (uint32_t)(brow * PAD + bk) * 2;
                uint32_t th[4], tl[4];
                ldm_x4(th, ad);
                ldm_x4(tl, ad + MSZ * 2);
                mma16816(acc[2*np],   qfh[kc], th[0], th[1]);
                mma16816(acc[2*np+1], qfh[kc], th[2], th[3]);
                mma16816(acc[2*np],   qfh[kc], tl[0], tl[1]);
                mma16816(acc[2*np+1], qfh[kc], tl[2], tl[3]);
                mma16816(acc[2*np],   qfl[kc], th[0], th[1]);
                mma16816(acc[2*np+1], qfl[kc], th[2], th[3]);
            }
        }

        // ---- online softmax update ----
        float tm0 = -1e30f, tm1 = -1e30f;
#pragma unroll
        for (int i = 0; i < 16; i++) {
            tm0 = fmaxf(tm0, fmaxf(acc[i][0], acc[i][1]));
            tm1 = fmaxf(tm1, fmaxf(acc[i][2], acc[i][3]));
        }
        tm0 = fmaxf(tm0, __shfl_xor_sync(0xffffffffu, tm0, 1));
        tm0 = fmaxf(tm0, __shfl_xor_sync(0xffffffffu, tm0, 2));
        tm1 = fmaxf(tm1, __shfl_xor_sync(0xffffffffu, tm1, 1));
        tm1 = fmaxf(tm1, __shfl_xor_sync(0xffffffffu, tm1, 2));

        float mn0 = fmaxf(m0, SM * tm0);
        float mn1 = fmaxf(m1, SM * tm1);
        float a0 = __expf(m0 - mn0);
        float a1 = __expf(m1 - mn1);
        m0 = mn0; m1 = mn1;

        float rs0 = 0.f, rs1 = 0.f;
#pragma unroll
        for (int i = 0; i < 16; i++) {
            float p0 = __expf(fmaf(SM, acc[i][0], -m0));
            float p1 = __expf(fmaf(SM, acc[i][1], -m0));
            float p2 = __expf(fmaf(SM, acc[i][2], -m1));
            float p3 = __expf(fmaf(SM, acc[i][3], -m1));
            acc[i][0] = p0; acc[i][1] = p1; acc[i][2] = p2; acc[i][3] = p3;
            rs0 += p0 + p1; rs1 += p2 + p3;
        }
        rs0 += __shfl_xor_sync(0xffffffffu, rs0, 1);
        rs0 += __shfl_xor_sync(0xffffffffu, rs0, 2);
        rs1 += __shfl_xor_sync(0xffffffffu, rs1, 1);
        rs1 += __shfl_xor_sync(0xffffffffu, rs1, 2);
        l0 = l0 * a0 + rs0;
        l1 = l1 * a1 + rs1;

#pragma unroll
        for (int i = 0; i < 8; i++) {
            O[i][0] *= a0; O[i][1] *= a0;
            O[i][2] *= a1; O[i][3] *= a1;
        }

        // ---- O += P @ V, P repacked from acc on the fly ----
#pragma unroll
        for (int kc2 = 0; kc2 < 8; kc2++) {
            uint32_t pah[4], pal[4];
            pah[0] = pack_split(acc[2*kc2][0],   acc[2*kc2][1],   pal[0]);
            pah[1] = pack_split(acc[2*kc2][2],   acc[2*kc2][3],   pal[1]);
            pah[2] = pack_split(acc[2*kc2+1][0], acc[2*kc2+1][1], pal[2]);
            pah[3] = pack_split(acc[2*kc2+1][2], acc[2*kc2+1][3], pal[3]);

            const int vrow = kc2 * 16 + (lane & 15);
#pragma unroll
            for (int dp = 0; dp < 4; dp++) {
                const int vcol = dp * 16 + ((lane >> 4) << 3);
                uint32_t ad = vb + (uint32_t)(vrow * PAD + vcol) * 2;
                uint32_t th[4], tl[4];
                ldm_x4_t(th, ad);
                ldm_x4_t(tl, ad + MSZ * 2);
                mma16816(O[2*dp],   pah, th[0], th[1]);
                mma16816(O[2*dp+1], pah, th[2], th[3]);
                mma16816(O[2*dp],   pah, tl[0], tl[1]);
                mma16816(O[2*dp+1], pah, tl[2], tl[3]);
                mma16816(O[2*dp],   pal, th[0], th[1]);
                mma16816(O[2*dp+1], pal, th[2], th[3]);
            }
        }

        if (t + 1 < NT) {
            CP_WAIT0();
            __syncthreads();
        }
    }

    // ---- epilogue: normalize, split, store ----
    const float inv0 = 1.0f / l0;
    const float inv1 = 1.0f / l1;
    const int row0 = q0 + m_w + (lane >> 2);
    const int colb = hh * HD + 2 * (lane & 3);
#pragma unroll
    for (int dt = 0; dt < 8; dt++) {
        int col = colb + dt * 8;
        size_t i0 = (tokbase + row0) * DIMC + col;
        size_t i1 = (tokbase + row0 + 8) * DIMC + col;
        uint32_t lo;
        uint32_t hi = pack_split(O[dt][0] * inv0, O[dt][1] * inv0, lo);
        *(uint32_t*)&Oh[i0] = hi;
        *(uint32_t*)&Ol[i0] = lo;
        hi = pack_split(O[dt][2] * inv1, O[dt][3] * inv1, lo);
        *(uint32_t*)&Oh[i1] = hi;
        *(uint32_t*)&Ol[i1] = lo;
    }
}

// ======================= split-fp16 mma.sync GEMM =======================
enum { ACT_NONE = 0, ACT_GELU = 1 };

template<int BN, int ACT, bool HAS_BIAS, bool OUT_SPLIT, bool HAS_RES>
__global__ void __launch_bounds__(256, 1)
mma_gemm(const h16* __restrict__ Ah, const h16* __restrict__ Al, int lda,
         const h16* __restrict__ Bh, const h16* __restrict__ Bl, int ldb,
         float* __restrict__ C, h16* __restrict__ Ch, h16* __restrict__ Cl,
         int ldc, int K,
         const float* __restrict__ bias,
         const float* __restrict__ res, int ldres)
{
    constexpr int BM = 128;
    constexpr int BK = 32;
    constexpr int PAD = 40;
    constexpr int WARPS_N = 4;
    constexpr int WM = 64;
    constexpr int WN = 32;
    constexpr int MT = 4;
    constexpr int NT = 4;
    constexpr int NP = 2;
    constexpr int AIT = 2;
    constexpr int BIT = BN * 4 / 256;
    constexpr int AL_OFF = 128 * PAD;
    constexpr int BH_OFF = 2 * 128 * PAD;
    constexpr int BL_OFF = 2 * 128 * PAD + BN * PAD;
    constexpr int STG_H  = 2 * 128 * PAD + 2 * BN * PAD;

    extern __shared__ h16 smem[];
    const int tid = threadIdx.x;
    const int wid = tid >> 5, lane = tid & 31;
    const int wn = wid % WARPS_N, wm = wid / WARPS_N;
    const int m_w = wm * WM, n_w = wn * WN;

    const int m0 = blockIdx.y * BM;
    const int n0 = blockIdx.x * BN;

    float acc[MT][NT][4];
#pragma unroll
    for (int i = 0; i < MT; i++)
#pragma unroll
        for (int j = 0; j < NT; j++)
#pragma unroll
            for (int q = 0; q < 4; q++) acc[i][j][q] = 0.f;

    const uint32_t sb = smem_u32(smem);

    {
        h16* d = smem;
#pragma unroll
        for (int i = 0; i < AIT; i++) {
            int idx = tid + i * 256, r = idx >> 2, cc = idx & 3;
            size_t src = (size_t)(m0 + r) * lda + cc * 8;
            *(uint4*)(d + r * PAD + cc * 8)          = *(const uint4*)(Ah + src);
            *(uint4*)(d + AL_OFF + r * PAD + cc * 8) = *(const uint4*)(Al + src);
        }
#pragma unroll
        for (int i = 0; i < BIT; i++) {
            int idx = tid + i * 256, r = idx >> 2, cc = idx & 3;
            size_t src = (size_t)(n0 + r) * ldb + cc * 8;
            *(uint4*)(d + BH_OFF + r * PAD + cc * 8) = *(const uint4*)(Bh + src);
            *(uint4*)(d + BL_OFF + r * PAD + cc * 8) = *(const uint4*)(Bl + src);
        }
    }
    __syncthreads();

    const int NC = K / BK;
    for (int c = 0; c < NC; ++c) {
        const int cur = c & 1;
        const bool pre = (c + 1 < NC);

        uint4 rAh[AIT], rAl[AIT], rBh[BIT], rBl[BIT];
        if (pre) {
            const int k0n = (c + 1) * BK;
#pragma unroll
            for (int i = 0; i < AIT; i++) {
                int idx = tid + i * 256, r = idx >> 2, cc = idx & 3;
                size_t src = (size_t)(m0 + r) * lda + k0n + cc * 8;
                rAh[i] = *(const uint4*)(Ah + src);
                rAl[i] = *(const uint4*)(Al + src);
            }
#pragma unroll
            for (int i = 0; i < BIT; i++) {
                int idx = tid + i * 256, r = idx >> 2, cc = idx & 3;
                size_t src = (size_t)(n0 + r) * ldb + k0n + cc * 8;
                rBh[i] = *(const uint4*)(Bh + src);
                rBl[i] = *(const uint4*)(Bl + src);
            }
        }

        {
            const uint32_t base = sb + (uint32_t)cur * STG_H * 2;
#pragma unroll
            for (int ks = 0; ks < 2; ks++) {
                uint32_t afh[MT][4], afl[MT][4];
                uint32_t bh[NT][2], bl[NT][2];
                const int arow = m_w + (lane & 15);
                const int akoff = ks * 16 + ((lane >> 4) << 3);
#pragma unroll
                for (int mi = 0; mi < MT; mi++) {
                    uint32_t ad = base + (uint32_t)((arow + mi * 16) * PAD + akoff) * 2;
                    ldm_x4(afh[mi], ad);
                    ldm_x4(afl[mi], ad + AL_OFF * 2);
                }
                const int brow = n_w + (lane & 7) + ((lane >> 4) << 3);
                const int bkoff = ks * 16 + ((lane >> 3) & 1) * 8;
#pragma unroll
                for (int np = 0; np < NP; np++) {
                    uint32_t bd = base + BH_OFF * 2
                                + (uint32_t)((brow + np * 16) * PAD + bkoff) * 2;
                    uint32_t t4[4];
                    ldm_x4(t4, bd);
                    bh[np*2][0] = t4[0]; bh[np*2][1] = t4[1];
                    bh[np*2+1][0] = t4[2]; bh[np*2+1][1] = t4[3];
                    ldm_x4(t4, bd + (BL_OFF - BH_OFF) * 2);
                    bl[np*2][0] = t4[0]; bl[np*2][1] = t4[1];
                    bl[np*2+1][0] = t4[2]; bl[np*2+1][1] = t4[3];
                }
#pragma unroll
                for (int mi = 0; mi < MT; mi++)
#pragma unroll
                    for (int ni = 0; ni < NT; ni++)
                        mma16816(acc[mi][ni], afh[mi], bh[ni][0], bh[ni][1]);
#pragma unroll
                for (int mi = 0; mi < MT; mi++)
#pragma unroll
                    for (int ni = 0; ni < NT; ni++)
                        mma16816(acc[mi][ni], afh[mi], bl[ni][0], bl[ni][1]);
#pragma unroll
                for (int mi = 0; mi < MT; mi++)
#pragma unroll
                    for (int ni = 0; ni < NT; ni++)
                        mma16816(acc[mi][ni], afl[mi], bh[ni][0], bh[ni][1]);
            }
        }

        if (pre) {
            h16* d = smem + (cur ^ 1) * STG_H;
#pragma unroll
            for (int i = 0; i < AIT; i++) {
                int idx = tid + i * 256, r = idx >> 2, cc = idx & 3;
                *(uint4*)(d + r * PAD + cc * 8)          = rAh[i];
                *(uint4*)(d + AL_OFF + r * PAD + cc * 8) = rAl[i];
            }
#pragma unroll
            for (int i = 0; i < BIT; i++) {
                int idx = tid + i * 256, r = idx >> 2, cc = idx & 3;
                *(uint4*)(d + BH_OFF + r * PAD + cc * 8) = rBh[i];
                *(uint4*)(d + BL_OFF + r * PAD + cc * 8) = rBl[i];
            }
        }
        __syncthreads();
    }

#pragma unroll
    for (int mi = 0; mi < MT; mi++) {
#pragma unroll
        for (int ni = 0; ni < NT; ni++) {
            int row0 = m0 + m_w + mi * 16 + (lane >> 2);
            int col  = n0 + n_w + ni * 8 + 2 * (lane & 3);
#pragma unroll
            for (int half = 0; half < 2; half++) {
                int row = row0 + half * 8;
                float v0 = acc[mi][ni][half * 2 + 0];
                float v1 = acc[mi][ni][half * 2 + 1];
                if (HAS_BIAS) {
                    float2 bb = *(const float2*)&bias[col];
                    v0 += bb.x; v1 += bb.y;
                }
                if (ACT == ACT_GELU) {
                    v0 = 0.5f * v0 * (1.0f + erff(v0 * 0.70710678118654752f));
                    v1 = 0.5f * v1 * (1.0f + erff(v1 * 0.70710678118654752f));
                }
                if (HAS_RES) {
                    float2 rr = *(const float2*)&res[(size_t)row * ldres + col];
                    v0 += rr.x; v1 += rr.y;
                }
                size_t idx = (size_t)row * ldc + col;
                if (!OUT_SPLIT) {
                    *(float2*)&C[idx] = make_float2(v0, v1);
                } else {
                    uint32_t lo;
                    uint32_t hi = pack_split(v0, v1, lo);
                    *(uint32_t*)&Ch[idx] = hi;
                    *(uint32_t*)&Cl[idx] = lo;
                }
            }
        }
    }
}

// ======================= host launcher =======================
extern "C" void kernel_launch(void* const* d_in, const int* in_sizes, int n_in,
                              void* d_out, int out_size)
{
    const float* x      = (const float*)d_in[0];
    const float* ln1_w  = (const float*)d_in[1];
    const float* ln1_b  = (const float*)d_in[2];
    const float* qkv_w  = (const float*)d_in[3];
    const float* qkv_b  = (const float*)d_in[4];
    const float* proj_w = (const float*)d_in[5];
    const float* proj_b = (const float*)d_in[6];
    const float* ln2_w  = (const float*)d_in[7];
    const float* ln2_b  = (const float*)d_in[8];
    const float* lin1_w = (const float*)d_in[9];
    const float* lin1_b = (const float*)d_in[10];
    const float* lin2_w = (const float*)d_in[11];
    const float* lin2_b = (const float*)d_in[12];
    float* out = (float*)d_out;

    h16 *ln_h, *ln_l, *qkv_h, *qkv_l, *at_h, *at_l, *h_h, *h_l;
    h16 *wqkv_h, *wqkv_l, *wpro_h, *wpro_l, *w1_h, *w1_l, *w2_h, *w2_l;
    float *x1;
    cudaGetSymbolAddress((void**)&ln_h, g_ln_h);   cudaGetSymbolAddress((void**)&ln_l, g_ln_l);
    cudaGetSymbolAddress((void**)&qkv_h, g_qkv_h); cudaGetSymbolAddress((void**)&qkv_l, g_qkv_l);
    cudaGetSymbolAddress((void**)&at_h, g_at_h);   cudaGetSymbolAddress((void**)&at_l, g_at_l);
    cudaGetSymbolAddress((void**)&x1, g_x1);
    cudaGetSymbolAddress((void**)&h_h, g_hh);      cudaGetSymbolAddress((void**)&h_l, g_hl);
    cudaGetSymbolAddress((void**)&wqkv_h, g_wqkv_h); cudaGetSymbolAddress((void**)&wqkv_l, g_wqkv_l);
    cudaGetSymbolAddress((void**)&wpro_h, g_wpro_h); cudaGetSymbolAddress((void**)&wpro_l, g_wpro_l);
    cudaGetSymbolAddress((void**)&w1_h, g_w1_h);   cudaGetSymbolAddress((void**)&w1_l, g_w1_l);
    cudaGetSymbolAddress((void**)&w2_h, g_w2_h);   cudaGetSymbolAddress((void**)&w2_l, g_w2_l);

    const int SM128 = 2 * (2 * 128 * 40 + 2 * 128 * 40) * 2;  // 81920
    const int SMATT = (2 + 8) * 128 * 72 * 2;                 // 184320

    auto* kQKV  = mma_gemm<128, ACT_NONE, true,  true,  false>;
    auto* kPROJ = mma_gemm<128, ACT_NONE, true,  false, true >;
    auto* kLIN1 = mma_gemm<128, ACT_GELU, true,  true,  false>;

    cudaFuncSetAttribute(kQKV,  cudaFuncAttributeMaxDynamicSharedMemorySize, SM128);
    cudaFuncSetAttribute(kPROJ, cudaFuncAttributeMaxDynamicSharedMemorySize, SM128);
    cudaFuncSetAttribute(kLIN1, cudaFuncAttributeMaxDynamicSharedMemorySize, SM128);
    cudaFuncSetAttribute(fattn_kernel, cudaFuncAttributeMaxDynamicSharedMemorySize, SMATT);

    // 0) weight transposes+splits
    wt_kernel<<<dim3(QKV_LD/32, DIMC/32), dim3(32,8)>>>(qkv_w,  DIMC, QKV_LD, wqkv_h, wqkv_l);
    wt_kernel<<<dim3(DIMC/32,   DIMC/32), dim3(32,8)>>>(proj_w, DIMC, DIMC,   wpro_h, wpro_l);
    wt_kernel<<<dim3(MLPD/32,   DIMC/32), dim3(32,8)>>>(lin1_w, DIMC, MLPD,   w1_h,   w1_l);
    wt_kernel<<<dim3(DIMC/32,   MLPD/32), dim3(32,8)>>>(lin2_w, MLPD, DIMC,   w2_h,   w2_l);

    // 1) LN1
    ln_kernel<<<TOKENS, 256>>>(x, ln1_w, ln1_b, ln_h, ln_l);

    // 2) qkv = ln @ qkv_w + qkv_b
    kQKV<<<dim3(QKV_LD/128, TOKENS/128), 256, SM128>>>(
        ln_h, ln_l, DIMC, wqkv_h, wqkv_l, DIMC,
        nullptr, qkv_h, qkv_l, QKV_LD, DIMC, qkv_b, nullptr, 0);

    // 3) fused attention: at = softmax(0.125 Q K^T) V
    fattn_kernel<<<dim3(SEQ/128, BH), 256, SMATT>>>(qkv_h, qkv_l, at_h, at_l);

    // 4) x1 = attn @ proj_w + proj_b + x
    kPROJ<<<dim3(DIMC/128, TOKENS/128), 256, SM128>>>(
        at_h, at_l, DIMC, wpro_h, wpro_l, DIMC,
        x1, nullptr, nullptr, DIMC, DIMC, proj_b, x, DIMC);

    // 5) LN2
    ln_kernel<<<TOKENS, 256>>>(x1, ln2_w, ln2_b, ln_h, ln_l);

    // 6) h = gelu(ln @ lin1_w + lin1_b)
    kLIN1<<<dim3(MLPD/128, TOKENS/128), 256, SM128>>>(
        ln_h, ln_l, DIMC, w1_h, w1_l, DIMC,
        nullptr, h_h, h_l, MLPD, DIMC, lin1_b, nullptr, 0);

    // 7) out = h @ lin2_w + lin2_b + x1
    kPROJ<<<dim3(DIMC/128, TOKENS/128), 256, SM128>>>(
        h_h, h_l, MLPD, w2_h, w2_l, MLPD,
        out, nullptr, nullptr, DIMC, MLPD, lin2_b, x1, DIMC);
}